// round 13
// baseline (speedup 1.0000x reference)
#include <cuda_runtime.h>
#include <cuda_fp16.h>
#include <cstdint>

#define BB 4
#define NN 16384
#define KK 16
#define CC 64
#define ROWS (BB * NN)          // 65536
#define GROUPS32P (ROWS / 32)   // proj: rounds of 32 rows = 2048
#define GROUPS8 (ROWS / 8)      // fused attn: groups of 8 points
#define TOTAL ((size_t)ROWS * CC)

// ---------------- scratch (static device globals) ---------------------------
__device__ __half2 g_kv[TOTAL];   // (ek, v) packed per (row, channel) — 16 MB
__device__ __half  g_h [TOTAL];   // pre-BN FFN output — 8 MB
__device__ float   g_sum [CC];    // BN stats accumulators
__device__ float   g_sum2[CC];

// ---------------- packed fp32x2 helpers (Blackwell FFMA2) --------------------
__device__ __forceinline__ unsigned long long pk2(float lo, float hi) {
    unsigned long long r;
    asm("mov.b64 %0, {%1, %2};" : "=l"(r) : "f"(lo), "f"(hi));
    return r;
}
__device__ __forceinline__ unsigned long long ffma2(
    unsigned long long a, unsigned long long b, unsigned long long c) {
    unsigned long long d;
    asm("fma.rn.f32x2 %0, %1, %2, %3;" : "=l"(d) : "l"(a), "l"(b), "l"(c));
    return d;
}
__device__ __forceinline__ float hsum2(unsigned long long a) {
    float lo, hi;
    asm("mov.b64 {%0, %1}, %2;" : "=f"(lo), "=f"(hi) : "l"(a));
    return lo + hi;
}

// ============================================================================
// Kernel 1: fused k/v projection, v5 (measured best: 37.7us). Unchanged.
// ============================================================================
__global__ void __launch_bounds__(256, 3) proj_kernel(
    const float* __restrict__ feat,
    const float* __restrict__ kw, const float* __restrict__ kb,
    const float* __restrict__ vw, const float* __restrict__ vb)
{
    __shared__ unsigned long long wsmK[32 * 64];  // [k2][c] K-pairs, 16 KB
    __shared__ unsigned long long wsmV[32 * 64];  // 16 KB
    __shared__ float xs[2][32 * 64];              // 32 staged rows, ping-pong, 16 KB

    const int tid  = threadIdx.x;
    const int lane = tid & 31;
    const int w    = tid >> 5;
    const int rw   = w & 3;                       // row subset 0..3
    const int c    = ((w >> 2) << 5) | lane;      // output channel 0..63

    if (blockIdx.x == 0 && tid < CC) { g_sum[tid] = 0.f; g_sum2[tid] = 0.f; }

    for (int i = tid; i < 32 * 64; i += 256) {
        const int k2 = i >> 6, ch = i & 63;
        wsmK[i] = pk2(kw[(2 * k2) * CC + ch], kw[(2 * k2 + 1) * CC + ch]);
        wsmV[i] = pk2(vw[(2 * k2) * CC + ch], vw[(2 * k2 + 1) * CC + ch]);
    }
    const float kbias = kb[c];
    const float vbias = vb[c];

    int g = blockIdx.x;
    {
        const float4* f4 = (const float4*)feat;
        ((float4*)xs[0])[tid]       = f4[(size_t)g * 512 + tid];
        ((float4*)xs[0])[tid + 256] = f4[(size_t)g * 512 + tid + 256];
    }
    __syncthreads();

    int buf = 0;
    for (; g < GROUPS32P; g += gridDim.x) {
        const int  gn  = g + gridDim.x;
        const bool has = (gn < GROUPS32P);
        float4 p0, p1;
        if (has) {
            const float4* f4 = (const float4*)feat;
            p0 = f4[(size_t)gn * 512 + tid];
            p1 = f4[(size_t)gn * 512 + tid + 256];
        }

        unsigned long long aK[8], aV[8];
#pragma unroll
        for (int r = 0; r < 8; r++) { aK[r] = 0ULL; aV[r] = 0ULL; }

        const float* xrow = xs[buf] + rw * (8 * 64);
#pragma unroll
        for (int k4 = 0; k4 < 16; k4++) {
            const unsigned long long wka = wsmK[(2 * k4) * 64 + c];
            const unsigned long long wkb = wsmK[(2 * k4 + 1) * 64 + c];
            const unsigned long long wva = wsmV[(2 * k4) * 64 + c];
            const unsigned long long wvb = wsmV[(2 * k4 + 1) * 64 + c];
#pragma unroll
            for (int r = 0; r < 8; r++) {
                ulonglong2 xq = *(const ulonglong2*)(xrow + r * 64 + k4 * 4);
                aK[r] = ffma2(xq.x, wka, aK[r]);
                aV[r] = ffma2(xq.x, wva, aV[r]);
                aK[r] = ffma2(xq.y, wkb, aK[r]);
                aV[r] = ffma2(xq.y, wvb, aV[r]);
            }
        }

        const size_t obase = (size_t)g * (32 * 64) + (size_t)rw * (8 * 64) + c;
#pragma unroll
        for (int r = 0; r < 8; r++) {
            float sk = hsum2(aK[r]) + kbias;
            float sv = hsum2(aV[r]) + vbias;
            float ek = __expf(-sk * 0.125f);      // exp(-k/8): q cancels in softmax
            g_kv[obase + r * 64] = __floats2half2_rn(ek, sv);
        }

        if (has) {
            ((float4*)xs[buf ^ 1])[tid]       = p0;
            ((float4*)xs[buf ^ 1])[tid + 256] = p1;
        }
        __syncthreads();
        buf ^= 1;
    }
}

// ============================================================================
// Kernel 2: fused local attention + FFN GEMV + BN stats, v3.
// Structure of the MEASURED-GOOD v1 (grid 1184, 3 barriers/group), but the
// per-thread rv[16]/ex..vy arrays are eliminated by a TWO-PASS gather:
//   pass 1: load 16 uint2, accumulate only the ek sums (values discarded)
//   pass 2: re-load the same addresses -> L1 HITS (warp footprint 4 KB;
//           32 warps x 4KB = 128 KB fits L1), compute the running max.
// A compiler memory fence between passes stops CSE from re-materializing the
// array. Register count drops to ~50 -> __launch_bounds__(256,4): 32 warps/SM
// (2x v1) to hide the ~240-cyc L2 gather latency. Math identical to v1.
// ============================================================================
__global__ void __launch_bounds__(256, 4) attn_ffn_kernel(
    const void* __restrict__ idx_raw,
    const float* __restrict__ fw, const float* __restrict__ fb)
{
    __shared__ float xs[8 * 64];     // ctx rows for 8 points
    __shared__ float ps[32 * 64];    // GEMV partials; reused for stat reduce

    const int tid  = threadIdx.x;
    const int lane = tid & 31;
    const int w    = tid >> 5;       // warp = which point in the group
    const int kq   = tid >> 6;       // GEMV: K-slice
    const int c    = tid & 63;       // GEMV: out channel

    const unsigned* pw = (const unsigned*)idx_raw;
    const bool is64 = ((pw[1] | pw[3] | pw[5] | pw[7]) == 0u);

    float fwreg[16];
#pragma unroll
    for (int i = 0; i < 16; i++) fwreg[i] = fw[(kq * 16 + i) * CC + c];
    const float fbias = fb[c];

    float acc_s = 0.f, acc_s2 = 0.f;

    for (int g = blockIdx.x; g < GROUPS8; g += gridDim.x) {
        // ---- neighbor indices (one warp per point) -------------------------
        const int p = g * 8 + w;
        const int b = p >> 14;                 // N = 16384
        int nb = 0;
        if (lane < KK) {
            long long iv = is64 ? ((const long long*)idx_raw)[(size_t)p * KK + lane]
                                : (long long)((const int*)idx_raw)[(size_t)p * KK + lane];
            nb = b * NN + (int)iv;
        }

        // ---- pass 1: gather, keep only the ek sums -------------------------
        float sx = 0.f, sy = 0.f;
#pragma unroll
        for (int j = 0; j < KK; j++) {
            int off = __shfl_sync(0xffffffffu, nb, j);
            uint2 r = ((const uint2*)(g_kv + (size_t)off * CC))[lane];
            sx += __low2float(*(__half2*)&r.x);
            sy += __low2float(*(__half2*)&r.y);
        }
        const float ix = __fdividef(1.f, sx);
        const float iy = __fdividef(1.f, sy);

        asm volatile("" ::: "memory");   // stop CSE: pass 2 must re-load (L1 hits)

        // ---- pass 2: re-gather from L1, compute max ------------------------
        float mx = -3.402823466e38f, my = -3.402823466e38f;
#pragma unroll
        for (int j = 0; j < KK; j++) {
            int off = __shfl_sync(0xffffffffu, nb, j);
            uint2 r = ((const uint2*)(g_kv + (size_t)off * CC))[lane];
            float2 f0 = __half22float2(*(__half2*)&r.x);
            float2 f1 = __half22float2(*(__half2*)&r.y);
            mx = fmaxf(mx, fmaf(f0.x, ix, -1.f) * f0.y);   // (softmax-1) * v
            my = fmaxf(my, fmaf(f1.x, iy, -1.f) * f1.y);
        }
        ((float2*)(xs + w * 64))[lane] = make_float2(mx, my);
        __syncthreads();

        // ---- FFN GEMV on the 8 ctx rows (x broadcast from smem) ------------
#pragma unroll
        for (int row = 0; row < 8; row++) {
            float pacc = 0.f;
            const float4* x4 = (const float4*)(xs + row * 64 + kq * 16);
#pragma unroll
            for (int i4 = 0; i4 < 4; i4++) {
                float4 xv = x4[i4];
                pacc = fmaf(xv.x, fwreg[i4 * 4 + 0], pacc);
                pacc = fmaf(xv.y, fwreg[i4 * 4 + 1], pacc);
                pacc = fmaf(xv.z, fwreg[i4 * 4 + 2], pacc);
                pacc = fmaf(xv.w, fwreg[i4 * 4 + 3], pacc);
            }
            ps[(row * 4 + kq) * 64 + c] = pacc;
        }
        __syncthreads();

        // ---- reduce partials, store h (fp16), accumulate stats -------------
#pragma unroll
        for (int rpass = 0; rpass < 2; rpass++) {
            const int row = (tid >> 6) + rpass * 4;
            float h = ps[(row * 4 + 0) * 64 + c] + ps[(row * 4 + 1) * 64 + c]
                    + ps[(row * 4 + 2) * 64 + c] + ps[(row * 4 + 3) * 64 + c] + fbias;
            g_h[(size_t)(g * 8 + row) * CC + c] = __float2half_rn(h);
            acc_s  += h;
            acc_s2 += h * h;
        }
        __syncthreads();
    }

    // ---- block-level stat reduction -> global atomics ----------------------
    ps[tid] = acc_s;  __syncthreads();
    if (tid < CC)
        atomicAdd(&g_sum[tid],  ps[tid] + ps[tid + 64] + ps[tid + 128] + ps[tid + 192]);
    __syncthreads();
    ps[tid] = acc_s2; __syncthreads();
    if (tid < CC)
        atomicAdd(&g_sum2[tid], ps[tid] + ps[tid + 64] + ps[tid + 128] + ps[tid + 192]);
}

// ============================================================================
// Kernel 3: finalize. (byte-identical to the passing kernel)
// ============================================================================
__global__ void __launch_bounds__(256) final_kernel(
    const float* __restrict__ feat,
    const float* __restrict__ gamma, const float* __restrict__ beta,
    float* __restrict__ out)
{
    __shared__ float s_scale[CC], s_shift[CC];
    if (threadIdx.x < CC) {
        const int  cc   = threadIdx.x;
        const float inv = 1.f / (float)ROWS;
        float m    = g_sum[cc] * inv;
        float var  = g_sum2[cc] * inv - m * m;
        float rstd = rsqrtf(var + 1e-5f);
        float sc   = rstd * gamma[cc];
        s_scale[cc] = sc;
        s_shift[cc] = beta[cc] - m * sc;
    }
    __syncthreads();

    const size_t total4 = TOTAL / 4;
    const uint2*  h2 = (const uint2*)g_h;
    const float4* f4 = (const float4*)feat;
    float4*       o4 = (float4*)out;
    const size_t stride = (size_t)gridDim.x * blockDim.x * 2;

    for (size_t i = ((size_t)blockIdx.x * blockDim.x + threadIdx.x) * 2;
         i + 1 < total4; i += stride) {
#pragma unroll
        for (int u = 0; u < 2; u++) {
            const size_t ii = i + u;
            const int c0 = (int)(ii & 15) * 4;
            uint2 hr = h2[ii];
            float4 f = f4[ii];
            float2 ha = __half22float2(*(__half2*)&hr.x);
            float2 hb = __half22float2(*(__half2*)&hr.y);
            float r0 = ha.x * s_scale[c0 + 0] + s_shift[c0 + 0];
            float r1 = ha.y * s_scale[c0 + 1] + s_shift[c0 + 1];
            float r2 = hb.x * s_scale[c0 + 2] + s_shift[c0 + 2];
            float r3 = hb.y * s_scale[c0 + 3] + s_shift[c0 + 3];
            r0 = (r0 >= 0.f) ? r0 : 0.2f * r0;
            r1 = (r1 >= 0.f) ? r1 : 0.2f * r1;
            r2 = (r2 >= 0.f) ? r2 : 0.2f * r2;
            r3 = (r3 >= 0.f) ? r3 : 0.2f * r3;
            o4[ii] = make_float4(f.x + r0, f.y + r1, f.z + r2, f.w + r3);
        }
    }
}

// ============================================================================
// launch: features(0) pos(1) qw(2) qb(3) kw(4) kb(5) vw(6) vb(7)
//         fw(8) fb(9) gamma(10) beta(11) idx(12)
// pos / qw / qb are mathematically unused (q cancels inside softmax).
// ============================================================================
extern "C" void kernel_launch(void* const* d_in, const int* in_sizes, int n_in,
                              void* d_out, int out_size)
{
    const float* feat  = (const float*)d_in[0];
    const float* kw    = (const float*)d_in[4];
    const float* kb    = (const float*)d_in[5];
    const float* vw    = (const float*)d_in[6];
    const float* vb    = (const float*)d_in[7];
    const float* fw    = (const float*)d_in[8];
    const float* fb    = (const float*)d_in[9];
    const float* gamma = (const float*)d_in[10];
    const float* beta  = (const float*)d_in[11];
    const void*  idx   = (const void*)d_in[12];
    float* out = (float*)d_out;

    proj_kernel     <<<444, 256>>>(feat, kw, kb, vw, vb);   // 3 CTAs x 148 SMs
    attn_ffn_kernel <<<1184, 256>>>(idx, fw, fb);           // v1 grid (measured good)
    final_kernel    <<<1024, 256>>>(feat, gamma, beta, out);
}

// round 14
// speedup vs baseline: 1.2269x; 1.2269x over previous
#include <cuda_runtime.h>
#include <cuda_fp16.h>
#include <cstdint>

#define BB 4
#define NN 16384
#define KK 16
#define CC 64
#define ROWS (BB * NN)          // 65536
#define GROUPS32P (ROWS / 32)   // proj: rounds of 32 rows = 2048
#define GROUPS8 (ROWS / 8)      // fused attn: groups of 8 points
#define TOTAL ((size_t)ROWS * CC)

// ---------------- scratch (static device globals) ---------------------------
__device__ __half2 g_kv[TOTAL];   // (ek, v) packed per (row, channel) — 16 MB
__device__ __half  g_h [TOTAL];   // pre-BN FFN output — 8 MB
__device__ float   g_sum [CC];    // BN stats accumulators
__device__ float   g_sum2[CC];

// ---------------- packed fp32x2 helpers (Blackwell FFMA2) --------------------
__device__ __forceinline__ unsigned long long pk2(float lo, float hi) {
    unsigned long long r;
    asm("mov.b64 %0, {%1, %2};" : "=l"(r) : "f"(lo), "f"(hi));
    return r;
}
__device__ __forceinline__ unsigned long long ffma2(
    unsigned long long a, unsigned long long b, unsigned long long c) {
    unsigned long long d;
    asm("fma.rn.f32x2 %0, %1, %2, %3;" : "=l"(d) : "l"(a), "l"(b), "l"(c));
    return d;
}
__device__ __forceinline__ float hsum2(unsigned long long a) {
    float lo, hi;
    asm("mov.b64 {%0, %1}, %2;" : "=f"(lo), "=f"(hi) : "l"(a));
    return lo + hi;
}

// ============================================================================
// Kernel 1: fused k/v projection, v5 (measured best: 37.7us). Unchanged.
// ============================================================================
__global__ void __launch_bounds__(256, 3) proj_kernel(
    const float* __restrict__ feat,
    const float* __restrict__ kw, const float* __restrict__ kb,
    const float* __restrict__ vw, const float* __restrict__ vb)
{
    __shared__ unsigned long long wsmK[32 * 64];  // [k2][c] K-pairs, 16 KB
    __shared__ unsigned long long wsmV[32 * 64];  // 16 KB
    __shared__ float xs[2][32 * 64];              // 32 staged rows, ping-pong, 16 KB

    const int tid  = threadIdx.x;
    const int lane = tid & 31;
    const int w    = tid >> 5;
    const int rw   = w & 3;                       // row subset 0..3
    const int c    = ((w >> 2) << 5) | lane;      // output channel 0..63

    if (blockIdx.x == 0 && tid < CC) { g_sum[tid] = 0.f; g_sum2[tid] = 0.f; }

    for (int i = tid; i < 32 * 64; i += 256) {
        const int k2 = i >> 6, ch = i & 63;
        wsmK[i] = pk2(kw[(2 * k2) * CC + ch], kw[(2 * k2 + 1) * CC + ch]);
        wsmV[i] = pk2(vw[(2 * k2) * CC + ch], vw[(2 * k2 + 1) * CC + ch]);
    }
    const float kbias = kb[c];
    const float vbias = vb[c];

    int g = blockIdx.x;
    {
        const float4* f4 = (const float4*)feat;
        ((float4*)xs[0])[tid]       = f4[(size_t)g * 512 + tid];
        ((float4*)xs[0])[tid + 256] = f4[(size_t)g * 512 + tid + 256];
    }
    __syncthreads();

    int buf = 0;
    for (; g < GROUPS32P; g += gridDim.x) {
        const int  gn  = g + gridDim.x;
        const bool has = (gn < GROUPS32P);
        float4 p0, p1;
        if (has) {
            const float4* f4 = (const float4*)feat;
            p0 = f4[(size_t)gn * 512 + tid];
            p1 = f4[(size_t)gn * 512 + tid + 256];
        }

        unsigned long long aK[8], aV[8];
#pragma unroll
        for (int r = 0; r < 8; r++) { aK[r] = 0ULL; aV[r] = 0ULL; }

        const float* xrow = xs[buf] + rw * (8 * 64);
#pragma unroll
        for (int k4 = 0; k4 < 16; k4++) {
            const unsigned long long wka = wsmK[(2 * k4) * 64 + c];
            const unsigned long long wkb = wsmK[(2 * k4 + 1) * 64 + c];
            const unsigned long long wva = wsmV[(2 * k4) * 64 + c];
            const unsigned long long wvb = wsmV[(2 * k4 + 1) * 64 + c];
#pragma unroll
            for (int r = 0; r < 8; r++) {
                ulonglong2 xq = *(const ulonglong2*)(xrow + r * 64 + k4 * 4);
                aK[r] = ffma2(xq.x, wka, aK[r]);
                aV[r] = ffma2(xq.x, wva, aV[r]);
                aK[r] = ffma2(xq.y, wkb, aK[r]);
                aV[r] = ffma2(xq.y, wvb, aV[r]);
            }
        }

        const size_t obase = (size_t)g * (32 * 64) + (size_t)rw * (8 * 64) + c;
#pragma unroll
        for (int r = 0; r < 8; r++) {
            float sk = hsum2(aK[r]) + kbias;
            float sv = hsum2(aV[r]) + vbias;
            float ek = __expf(-sk * 0.125f);      // exp(-k/8): q cancels in softmax
            g_kv[obase + r * 64] = __floats2half2_rn(ek, sv);
        }

        if (has) {
            ((float4*)xs[buf ^ 1])[tid]       = p0;
            ((float4*)xs[buf ^ 1])[tid + 256] = p1;
        }
        __syncthreads();
        buf ^= 1;
    }
}

// ============================================================================
// Kernel 2: fused local attention + FFN GEMV + BN stats, v4.
// Identical to the MEASURED-BEST v1 (grid 1184, 3 barriers, single-pass
// gather) with ONE delta: gathered (ek,v) kept as RAW uint2 (32 regs instead
// of 64 unpacked floats); the max loop re-unpacks from REGISTERS (pure ALU,
// no memory reload). No forced CTA floor — __launch_bounds__(256) lets ptxas
// pick its natural register count: <=80 regs -> 3 CTAs/SM free upside;
// otherwise exactly v1's 2 CTAs (bounded downside).
// ============================================================================
__global__ void __launch_bounds__(256) attn_ffn_kernel(
    const void* __restrict__ idx_raw,
    const float* __restrict__ fw, const float* __restrict__ fb)
{
    __shared__ float xs[8 * 64];     // ctx rows for 8 points
    __shared__ float ps[32 * 64];    // GEMV partials; reused for stat reduce

    const int tid  = threadIdx.x;
    const int lane = tid & 31;
    const int w    = tid >> 5;       // warp = which point in the group
    const int kq   = tid >> 6;       // GEMV: K-slice
    const int c    = tid & 63;       // GEMV: out channel

    const unsigned* pw = (const unsigned*)idx_raw;
    const bool is64 = ((pw[1] | pw[3] | pw[5] | pw[7]) == 0u);

    float fwreg[16];
#pragma unroll
    for (int i = 0; i < 16; i++) fwreg[i] = fw[(kq * 16 + i) * CC + c];
    const float fbias = fb[c];

    float acc_s = 0.f, acc_s2 = 0.f;

    for (int g = blockIdx.x; g < GROUPS8; g += gridDim.x) {
        // ---- attention: one warp per point, lane owns channels 2l, 2l+1 ----
        const int p = g * 8 + w;
        const int b = p >> 14;                 // N = 16384
        int nb = 0;
        if (lane < KK) {
            long long iv = is64 ? ((const long long*)idx_raw)[(size_t)p * KK + lane]
                                : (long long)((const int*)idx_raw)[(size_t)p * KK + lane];
            nb = b * NN + (int)iv;
        }

        // single-pass gather; keep raw uint2 (32 regs, half of v1's arrays)
        uint2 rv[KK];
        float sx = 0.f, sy = 0.f;
#pragma unroll
        for (int j = 0; j < KK; j++) {
            int off = __shfl_sync(0xffffffffu, nb, j);
            uint2 r = ((const uint2*)(g_kv + (size_t)off * CC))[lane];
            rv[j] = r;
            sx += __low2float(*(__half2*)&r.x);
            sy += __low2float(*(__half2*)&r.y);
        }
        const float ix = __fdividef(1.f, sx);
        const float iy = __fdividef(1.f, sy);

        float mx = -3.402823466e38f, my = -3.402823466e38f;
#pragma unroll
        for (int j = 0; j < KK; j++) {
            float2 f0 = __half22float2(*(__half2*)&rv[j].x);   // register unpack
            float2 f1 = __half22float2(*(__half2*)&rv[j].y);
            mx = fmaxf(mx, fmaf(f0.x, ix, -1.f) * f0.y);       // (softmax-1) * v
            my = fmaxf(my, fmaf(f1.x, iy, -1.f) * f1.y);
        }
        ((float2*)(xs + w * 64))[lane] = make_float2(mx, my);
        __syncthreads();

        // ---- FFN GEMV on the 8 ctx rows (x broadcast from smem) ------------
#pragma unroll
        for (int row = 0; row < 8; row++) {
            float pacc = 0.f;
            const float4* x4 = (const float4*)(xs + row * 64 + kq * 16);
#pragma unroll
            for (int i4 = 0; i4 < 4; i4++) {
                float4 xv = x4[i4];
                pacc = fmaf(xv.x, fwreg[i4 * 4 + 0], pacc);
                pacc = fmaf(xv.y, fwreg[i4 * 4 + 1], pacc);
                pacc = fmaf(xv.z, fwreg[i4 * 4 + 2], pacc);
                pacc = fmaf(xv.w, fwreg[i4 * 4 + 3], pacc);
            }
            ps[(row * 4 + kq) * 64 + c] = pacc;
        }
        __syncthreads();

        // ---- reduce partials, store h (fp16), accumulate stats -------------
#pragma unroll
        for (int rpass = 0; rpass < 2; rpass++) {
            const int row = (tid >> 6) + rpass * 4;
            float h = ps[(row * 4 + 0) * 64 + c] + ps[(row * 4 + 1) * 64 + c]
                    + ps[(row * 4 + 2) * 64 + c] + ps[(row * 4 + 3) * 64 + c] + fbias;
            g_h[(size_t)(g * 8 + row) * CC + c] = __float2half_rn(h);
            acc_s  += h;
            acc_s2 += h * h;
        }
        __syncthreads();
    }

    // ---- block-level stat reduction -> global atomics ----------------------
    ps[tid] = acc_s;  __syncthreads();
    if (tid < CC)
        atomicAdd(&g_sum[tid],  ps[tid] + ps[tid + 64] + ps[tid + 128] + ps[tid + 192]);
    __syncthreads();
    ps[tid] = acc_s2; __syncthreads();
    if (tid < CC)
        atomicAdd(&g_sum2[tid], ps[tid] + ps[tid + 64] + ps[tid + 128] + ps[tid + 192]);
}

// ============================================================================
// Kernel 3: finalize. (byte-identical to the passing kernel)
// ============================================================================
__global__ void __launch_bounds__(256) final_kernel(
    const float* __restrict__ feat,
    const float* __restrict__ gamma, const float* __restrict__ beta,
    float* __restrict__ out)
{
    __shared__ float s_scale[CC], s_shift[CC];
    if (threadIdx.x < CC) {
        const int  cc   = threadIdx.x;
        const float inv = 1.f / (float)ROWS;
        float m    = g_sum[cc] * inv;
        float var  = g_sum2[cc] * inv - m * m;
        float rstd = rsqrtf(var + 1e-5f);
        float sc   = rstd * gamma[cc];
        s_scale[cc] = sc;
        s_shift[cc] = beta[cc] - m * sc;
    }
    __syncthreads();

    const size_t total4 = TOTAL / 4;
    const uint2*  h2 = (const uint2*)g_h;
    const float4* f4 = (const float4*)feat;
    float4*       o4 = (float4*)out;
    const size_t stride = (size_t)gridDim.x * blockDim.x * 2;

    for (size_t i = ((size_t)blockIdx.x * blockDim.x + threadIdx.x) * 2;
         i + 1 < total4; i += stride) {
#pragma unroll
        for (int u = 0; u < 2; u++) {
            const size_t ii = i + u;
            const int c0 = (int)(ii & 15) * 4;
            uint2 hr = h2[ii];
            float4 f = f4[ii];
            float2 ha = __half22float2(*(__half2*)&hr.x);
            float2 hb = __half22float2(*(__half2*)&hr.y);
            float r0 = ha.x * s_scale[c0 + 0] + s_shift[c0 + 0];
            float r1 = ha.y * s_scale[c0 + 1] + s_shift[c0 + 1];
            float r2 = hb.x * s_scale[c0 + 2] + s_shift[c0 + 2];
            float r3 = hb.y * s_scale[c0 + 3] + s_shift[c0 + 3];
            r0 = (r0 >= 0.f) ? r0 : 0.2f * r0;
            r1 = (r1 >= 0.f) ? r1 : 0.2f * r1;
            r2 = (r2 >= 0.f) ? r2 : 0.2f * r2;
            r3 = (r3 >= 0.f) ? r3 : 0.2f * r3;
            o4[ii] = make_float4(f.x + r0, f.y + r1, f.z + r2, f.w + r3);
        }
    }
}

// ============================================================================
// launch: features(0) pos(1) qw(2) qb(3) kw(4) kb(5) vw(6) vb(7)
//         fw(8) fb(9) gamma(10) beta(11) idx(12)
// pos / qw / qb are mathematically unused (q cancels inside softmax).
// ============================================================================
extern "C" void kernel_launch(void* const* d_in, const int* in_sizes, int n_in,
                              void* d_out, int out_size)
{
    const float* feat  = (const float*)d_in[0];
    const float* kw    = (const float*)d_in[4];
    const float* kb    = (const float*)d_in[5];
    const float* vw    = (const float*)d_in[6];
    const float* vb    = (const float*)d_in[7];
    const float* fw    = (const float*)d_in[8];
    const float* fb    = (const float*)d_in[9];
    const float* gamma = (const float*)d_in[10];
    const float* beta  = (const float*)d_in[11];
    const void*  idx   = (const void*)d_in[12];
    float* out = (float*)d_out;

    proj_kernel     <<<444, 256>>>(feat, kw, kb, vw, vb);   // 3 CTAs x 148 SMs
    attn_ffn_kernel <<<1184, 256>>>(idx, fw, fb);           // v1 grid (measured good)
    final_kernel    <<<1024, 256>>>(feat, gamma, beta, out);
}